// round 1
// baseline (speedup 1.0000x reference)
#include <cuda_runtime.h>
#include <math.h>

#define D_MODEL   1024
#define N_HEADS   16
#define D_QKV     64
#define D_FF      4096
#define N_LAYERS  6
#define SEQ       1024
#define BATCH     8
#define TOK       (BATCH*SEQ)     /* 8192 tokens */
#define N_ACTIONS 16

// ---------------- static device scratch (no allocs allowed) ----------------
__device__ float g_h[TOK * D_MODEL];            // 32 MB: residual stream
__device__ float g_qkv[TOK * 3 * D_MODEL];      // 96 MB: fused qkv [tok][3072]
__device__ float g_ctx[TOK * D_MODEL];          // 32 MB: attention output (B,L,H,Dq)
__device__ float g_buf1[TOK * D_FF];            // 128 MB: att_out / ff mid
__device__ float g_buf2[TOK * D_MODEL];         // 32 MB: ff out
__device__ float g_wpack[D_MODEL * 3 * D_MODEL];// 12 MB: packed per-layer QKV weights

// ---------------- embedding + positional encoding ----------------
__global__ void embed_kernel(const int* __restrict__ x, const float* __restrict__ embed)
{
    int t   = blockIdx.x;            // token 0..8191
    int tid = threadIdx.x;           // 256 threads, 1 float4 each
    int l   = t & (SEQ - 1);
    int tok = x[t];
    int j   = tid * 4;               // even

    float4 ev = *(const float4*)(embed + (size_t)tok * D_MODEL + j);
    float pos = (float)(l + 1);
    // divisor = 10000^(j/1024); ang = pos/divisor; pe = [sin,cos] interleaved
    float ang0 = pos / powf(10000.0f, (float)j       * (1.0f / D_MODEL));
    float ang1 = pos / powf(10000.0f, (float)(j + 2) * (1.0f / D_MODEL));

    float4 o;
    o.x = ev.x * 32.0f + sinf(ang0);
    o.y = ev.y * 32.0f + cosf(ang0);
    o.z = ev.z * 32.0f + sinf(ang1);
    o.w = ev.w * 32.0f + cosf(ang1);
    *(float4*)(g_h + (size_t)t * D_MODEL + j) = o;
}

// ---------------- pack Wq/Wk/Wv[layer] into [K=1024][N=3072] row-major ----------------
__global__ void pack_qkv_kernel(const float* __restrict__ Wq, const float* __restrict__ Wk,
                                const float* __restrict__ Wv, int layer)
{
    int idx = blockIdx.x * 256 + threadIdx.x;   // 1024*3072 elements
    int k = idx / (3 * D_MODEL);
    int n = idx % (3 * D_MODEL);
    int sel = n >> 10;
    int r   = n & 1023;
    int h   = r >> 6;
    int d   = r & 63;
    const float* W = (sel == 0) ? Wq : (sel == 1) ? Wk : Wv;
    g_wpack[idx] = W[(((size_t)layer * N_HEADS + h) * D_MODEL + k) * D_QKV + d];
}

// ---------------- tiled SGEMM: C[M,N] = A[M,K] @ B[K,N] (+bias)(relu) ----------------
#define BM 128
#define BN 128
#define BK 16
__global__ void __launch_bounds__(256)
sgemm_kernel(const float* __restrict__ A, const float* __restrict__ B,
             const float* __restrict__ bias, float* __restrict__ C,
             int M, int N, int K, int do_relu)
{
    __shared__ float As[BK][BM + 4];
    __shared__ float Bs[BK][BN + 4];

    const int tid = threadIdx.x;
    const int tx  = tid & 15;        // 16 col-threads
    const int ty  = tid >> 4;        // 16 row-threads
    const int bx  = blockIdx.x;
    const int by  = blockIdx.y;

    const float* Ab = A + (size_t)by * BM * K;
    const float* Bb = B + (size_t)bx * BN;

    const int arow = tid >> 2;             // 0..63
    const int acol = (tid & 3) << 2;       // 0,4,8,12
    const int brow = tid >> 5;             // 0..7
    const int bcol = (tid & 31) << 2;      // 0..124

    float acc[8][8];
    #pragma unroll
    for (int i = 0; i < 8; i++)
        #pragma unroll
        for (int j = 0; j < 8; j++) acc[i][j] = 0.0f;

    for (int k0 = 0; k0 < K; k0 += BK) {
        float4 a0 = *(const float4*)(Ab + (size_t)arow        * K + k0 + acol);
        float4 a1 = *(const float4*)(Ab + (size_t)(arow + 64) * K + k0 + acol);
        float4 b0 = *(const float4*)(Bb + (size_t)(k0 + brow)     * N + bcol);
        float4 b1 = *(const float4*)(Bb + (size_t)(k0 + brow + 8) * N + bcol);

        As[acol + 0][arow]      = a0.x;
        As[acol + 1][arow]      = a0.y;
        As[acol + 2][arow]      = a0.z;
        As[acol + 3][arow]      = a0.w;
        As[acol + 0][arow + 64] = a1.x;
        As[acol + 1][arow + 64] = a1.y;
        As[acol + 2][arow + 64] = a1.z;
        As[acol + 3][arow + 64] = a1.w;
        *(float4*)&Bs[brow][bcol]     = b0;
        *(float4*)&Bs[brow + 8][bcol] = b1;
        __syncthreads();

        #pragma unroll
        for (int kk = 0; kk < BK; kk++) {
            float ar[8], br[8];
            *(float4*)&ar[0] = *(const float4*)&As[kk][ty * 4];
            *(float4*)&ar[4] = *(const float4*)&As[kk][64 + ty * 4];
            *(float4*)&br[0] = *(const float4*)&Bs[kk][tx * 4];
            *(float4*)&br[4] = *(const float4*)&Bs[kk][64 + tx * 4];
            #pragma unroll
            for (int i = 0; i < 8; i++)
                #pragma unroll
                for (int j = 0; j < 8; j++)
                    acc[i][j] += ar[i] * br[j];
        }
        __syncthreads();
    }

    // epilogue: 2x2 quadrants of 4x4
    #pragma unroll
    for (int hm = 0; hm < 2; hm++) {
        #pragma unroll
        for (int i = 0; i < 4; i++) {
            int row = by * BM + hm * 64 + ty * 4 + i;
            #pragma unroll
            for (int hn = 0; hn < 2; hn++) {
                int col = bx * BN + hn * 64 + tx * 4;
                float4 v;
                v.x = acc[hm * 4 + i][hn * 4 + 0];
                v.y = acc[hm * 4 + i][hn * 4 + 1];
                v.z = acc[hm * 4 + i][hn * 4 + 2];
                v.w = acc[hm * 4 + i][hn * 4 + 3];
                if (bias) {
                    float4 bv = *(const float4*)(bias + col);
                    v.x += bv.x; v.y += bv.y; v.z += bv.z; v.w += bv.w;
                }
                if (do_relu) {
                    v.x = fmaxf(v.x, 0.0f); v.y = fmaxf(v.y, 0.0f);
                    v.z = fmaxf(v.z, 0.0f); v.w = fmaxf(v.w, 0.0f);
                }
                *(float4*)(C + (size_t)row * N + col) = v;
            }
        }
    }
}

// ---------------- fused attention (online softmax, flash-style) ----------------
// grid: (SEQ/AQ, B*H); block: 128 threads, one query row per thread
#define AQ 128
#define AK 64
__global__ void __launch_bounds__(128)
attn_kernel(const int* __restrict__ mask)
{
    __shared__ float Ks[AK][D_QKV];          // 16 KB
    __shared__ float Vs[AK][D_QKV];          // 16 KB
    __shared__ unsigned char Ms[AQ][AK];     // 8 KB

    const int tid  = threadIdx.x;
    const int bh   = blockIdx.y;
    const int b    = bh >> 4;
    const int h    = bh & 15;
    const int q0   = blockIdx.x * AQ;
    const int qrow = q0 + tid;

    const float* qp = g_qkv + (size_t)(b * SEQ + qrow) * (3 * D_MODEL) + h * 64;
    float q[64];
    #pragma unroll
    for (int i = 0; i < 16; i++) {
        float4 v = *(const float4*)(qp + i * 4);
        q[i*4+0] = v.x; q[i*4+1] = v.y; q[i*4+2] = v.z; q[i*4+3] = v.w;
    }
    float acc[64];
    #pragma unroll
    for (int i = 0; i < 64; i++) acc[i] = 0.0f;
    float m_run = -1e30f, l_run = 0.0f;

    const int* mb = mask + (size_t)b * SEQ * SEQ;

    for (int j0 = 0; j0 < SEQ; j0 += AK) {
        // K/V tiles: 64 rows x 64 floats each; 8 float4-pairs per thread
        #pragma unroll
        for (int it = 0; it < 8; it++) {
            int idx = tid + it * 128;        // 0..1023
            int r = idx >> 4;
            int c = (idx & 15) << 2;
            const float* kp = g_qkv + (size_t)(b * SEQ + j0 + r) * (3 * D_MODEL) + D_MODEL + h * 64 + c;
            *(float4*)&Ks[r][c] = *(const float4*)kp;
            *(float4*)&Vs[r][c] = *(const float4*)(kp + D_MODEL);
        }
        // mask tile: 128 x 64 ints -> bytes
        #pragma unroll
        for (int it = 0; it < 16; it++) {
            int idx = tid + it * 128;        // 0..2047
            int r = idx >> 4;                // 0..127
            int c = (idx & 15) << 2;
            int4 mv = *(const int4*)(mb + (size_t)(q0 + r) * SEQ + j0 + c);
            Ms[r][c + 0] = (unsigned char)(mv.x != 0);
            Ms[r][c + 1] = (unsigned char)(mv.y != 0);
            Ms[r][c + 2] = (unsigned char)(mv.z != 0);
            Ms[r][c + 3] = (unsigned char)(mv.w != 0);
        }
        __syncthreads();

        #pragma unroll 1
        for (int j = 0; j < AK; j++) {
            float s = 0.0f;
            #pragma unroll
            for (int d4 = 0; d4 < 16; d4++) {
                float4 kv = *(const float4*)&Ks[j][d4 * 4];
                s += q[d4*4+0]*kv.x + q[d4*4+1]*kv.y + q[d4*4+2]*kv.z + q[d4*4+3]*kv.w;
            }
            s = Ms[tid][j] ? s * 0.125f : -1e9f;
            if (s > m_run) {                  // rare rescale (record maxima only)
                float corr = __expf(m_run - s);
                m_run = s;
                l_run *= corr;
                #pragma unroll
                for (int d = 0; d < 64; d++) acc[d] *= corr;
            }
            float p = __expf(s - m_run);
            l_run += p;
            #pragma unroll
            for (int d4 = 0; d4 < 16; d4++) {
                float4 vv = *(const float4*)&Vs[j][d4 * 4];
                acc[d4*4+0] += p * vv.x;
                acc[d4*4+1] += p * vv.y;
                acc[d4*4+2] += p * vv.z;
                acc[d4*4+3] += p * vv.w;
            }
        }
        __syncthreads();
    }

    float inv = 1.0f / l_run;
    float* op = g_ctx + (size_t)(b * SEQ + qrow) * D_MODEL + h * 64;
    #pragma unroll
    for (int i = 0; i < 16; i++) {
        float4 v;
        v.x = acc[i*4+0] * inv; v.y = acc[i*4+1] * inv;
        v.z = acc[i*4+2] * inv; v.w = acc[i*4+3] * inv;
        *(float4*)(op + i * 4) = v;
    }
}

// ---------------- residual add + layernorm (in-place on g_h safe: row-local) ----------------
__global__ void ln_kernel(const float* __restrict__ resid, const float* __restrict__ add,
                          const float* __restrict__ sc, const float* __restrict__ bi,
                          float* __restrict__ out)
{
    __shared__ float ssum[8], ssq[8];
    int row = blockIdx.x, tid = threadIdx.x;   // 256 threads, 1 float4 each
    int c = tid * 4;
    float4 hv = *(const float4*)(resid + (size_t)row * D_MODEL + c);
    float4 av = *(const float4*)(add   + (size_t)row * D_MODEL + c);
    float4 r = make_float4(hv.x + av.x, hv.y + av.y, hv.z + av.z, hv.w + av.w);
    float s = r.x + r.y + r.z + r.w;
    float qq = r.x*r.x + r.y*r.y + r.z*r.z + r.w*r.w;
    #pragma unroll
    for (int o = 16; o > 0; o >>= 1) {
        s  += __shfl_xor_sync(0xffffffffu, s,  o);
        qq += __shfl_xor_sync(0xffffffffu, qq, o);
    }
    int w = tid >> 5;
    if ((tid & 31) == 0) { ssum[w] = s; ssq[w] = qq; }
    __syncthreads();
    float ts = 0.0f, tq = 0.0f;
    #pragma unroll
    for (int i = 0; i < 8; i++) { ts += ssum[i]; tq += ssq[i]; }
    float mu   = ts * (1.0f / D_MODEL);
    float var  = tq * (1.0f / D_MODEL) - mu * mu;
    float rstd = rsqrtf(var + 1e-5f);
    float4 scv = *(const float4*)(sc + c);
    float4 biv = *(const float4*)(bi + c);
    float4 o;
    o.x = (r.x - mu) * rstd * scv.x + biv.x;
    o.y = (r.y - mu) * rstd * scv.y + biv.y;
    o.z = (r.z - mu) * rstd * scv.z + biv.z;
    o.w = (r.w - mu) * rstd * scv.w + biv.w;
    *(float4*)(out + (size_t)row * D_MODEL + c) = o;
}

// ---------------- final head: logits of last token + log_softmax ----------------
__global__ void head_kernel(const float* __restrict__ ow, const float* __restrict__ ob,
                            float* __restrict__ out)
{
    int tid = threadIdx.x;           // 128 = 8 batches * 16 actions
    int b = tid >> 4, a = tid & 15;
    const float* hr = g_h + ((size_t)b * SEQ + (SEQ - 1)) * D_MODEL;
    float acc = 0.0f;
    for (int k = 0; k < D_MODEL; k++) acc += hr[k] * ow[k * N_ACTIONS + a];
    acc += ob[a];
    float m = acc;
    #pragma unroll
    for (int o = 8; o > 0; o >>= 1) m = fmaxf(m, __shfl_xor_sync(0xffffffffu, m, o, 16));
    float e = expf(acc - m), sum = e;
    #pragma unroll
    for (int o = 8; o > 0; o >>= 1) sum += __shfl_xor_sync(0xffffffffu, sum, o, 16);
    out[b * N_ACTIONS + a] = acc - m - logf(sum);
}

// ---------------- launch ----------------
extern "C" void kernel_launch(void* const* d_in, const int* in_sizes, int n_in,
                              void* d_out, int out_size)
{
    const int*   x     = (const int*)d_in[0];
    const int*   mask  = (const int*)d_in[1];
    const float* embed = (const float*)d_in[2];
    const float* Wq    = (const float*)d_in[3];
    const float* Wk    = (const float*)d_in[4];
    const float* Wv    = (const float*)d_in[5];
    const float* Wo_w  = (const float*)d_in[6];
    const float* Wo_b  = (const float*)d_in[7];
    const float* ln1s  = (const float*)d_in[8];
    const float* ln1b  = (const float*)d_in[9];
    const float* ffw1  = (const float*)d_in[10];
    const float* ffb1  = (const float*)d_in[11];
    const float* ffw2  = (const float*)d_in[12];
    const float* ffb2  = (const float*)d_in[13];
    const float* ln2s  = (const float*)d_in[14];
    const float* ln2b  = (const float*)d_in[15];
    const float* ow    = (const float*)d_in[16];
    const float* ob    = (const float*)d_in[17];
    float* out = (float*)d_out;

    float *h, *qkv, *ctx, *buf1, *buf2, *wpack;
    cudaGetSymbolAddress((void**)&h,     g_h);
    cudaGetSymbolAddress((void**)&qkv,   g_qkv);
    cudaGetSymbolAddress((void**)&ctx,   g_ctx);
    cudaGetSymbolAddress((void**)&buf1,  g_buf1);
    cudaGetSymbolAddress((void**)&buf2,  g_buf2);
    cudaGetSymbolAddress((void**)&wpack, g_wpack);

    embed_kernel<<<TOK, 256>>>(x, embed);

    for (int i = 0; i < N_LAYERS; i++) {
        pack_qkv_kernel<<<(D_MODEL * 3 * D_MODEL) / 256, 256>>>(Wq, Wk, Wv, i);
        sgemm_kernel<<<dim3((3 * D_MODEL) / BN, TOK / BM), 256>>>(
            h, wpack, nullptr, qkv, TOK, 3 * D_MODEL, D_MODEL, 0);
        attn_kernel<<<dim3(SEQ / AQ, BATCH * N_HEADS), 128>>>(mask);
        sgemm_kernel<<<dim3(D_MODEL / BN, TOK / BM), 256>>>(
            ctx, Wo_w + (size_t)i * D_MODEL * D_MODEL, Wo_b + (size_t)i * D_MODEL,
            buf1, TOK, D_MODEL, D_MODEL, 0);
        ln_kernel<<<TOK, 256>>>(h, buf1, ln1s + (size_t)i * D_MODEL, ln1b + (size_t)i * D_MODEL, h);
        sgemm_kernel<<<dim3(D_FF / BN, TOK / BM), 256>>>(
            h, ffw1 + (size_t)i * D_MODEL * D_FF, ffb1 + (size_t)i * D_FF,
            buf1, TOK, D_FF, D_MODEL, 1);
        sgemm_kernel<<<dim3(D_MODEL / BN, TOK / BM), 256>>>(
            buf1, ffw2 + (size_t)i * D_FF * D_MODEL, ffb2 + (size_t)i * D_MODEL,
            buf2, TOK, D_MODEL, D_FF, 0);
        ln_kernel<<<TOK, 256>>>(h, buf2, ln2s + (size_t)i * D_MODEL, ln2b + (size_t)i * D_MODEL, h);
    }

    head_kernel<<<1, 128>>>(ow, ob, out);
}

// round 8
// speedup vs baseline: 1.4979x; 1.4979x over previous
#include <cuda_runtime.h>
#include <math.h>
#include <stdint.h>

#define D_MODEL   1024
#define N_HEADS   16
#define D_QKV     64
#define D_FF      4096
#define N_LAYERS  6
#define SEQ       1024
#define BATCH     8
#define TOK       (BATCH*SEQ)
#define N_ACTIONS 16

// ---------------- static device scratch ----------------
__device__ float g_h[TOK * D_MODEL];            // residual stream (fp32)
__device__ float g_qkv[TOK * 3 * D_MODEL];
__device__ float g_ctx[TOK * D_MODEL];
__device__ float g_buf1[TOK * D_FF];
__device__ float g_buf2[TOK * D_MODEL];
// transposed + tf32-rounded weights, [N][K] K-major
__device__ float g_wqkv[N_LAYERS * 3 * D_MODEL * D_MODEL];
__device__ float g_wot [N_LAYERS * D_MODEL * D_MODEL];
__device__ float g_w1t [N_LAYERS * D_FF * D_MODEL];
__device__ float g_w2t [N_LAYERS * D_MODEL * D_FF];

// tf32 round-to-nearest via pure integer ops (no exotic PTX).
// Idempotent: applying twice gives the same value.
__device__ __forceinline__ float tf32i(float x) {
    uint32_t u = __float_as_uint(x);
    u = (u + 0x00000FFFu + ((u >> 13) & 1u)) & 0xFFFFE000u;
    return __uint_as_float(u);
}

__device__ __forceinline__ void mma_tf32(float* c, const uint32_t* a, const uint32_t* b) {
    asm volatile(
        "mma.sync.aligned.m16n8k8.row.col.f32.tf32.tf32.f32 "
        "{%0,%1,%2,%3}, {%4,%5,%6,%7}, {%8,%9}, {%0,%1,%2,%3};"
        : "+f"(c[0]), "+f"(c[1]), "+f"(c[2]), "+f"(c[3])
        : "r"(a[0]), "r"(a[1]), "r"(a[2]), "r"(a[3]), "r"(b[0]), "r"(b[1]));
}

// ---------------- embedding + positional encoding (R1-identical) ----------------
__global__ void embed_kernel(const int* __restrict__ x, const float* __restrict__ embed)
{
    int t   = blockIdx.x;
    int tid = threadIdx.x;
    int l   = t & (SEQ - 1);
    int tok = x[t];
    int j   = tid * 4;

    float4 ev = *(const float4*)(embed + (size_t)tok * D_MODEL + j);
    float pos = (float)(l + 1);
    float ang0 = pos / powf(10000.0f, (float)j       * (1.0f / D_MODEL));
    float ang1 = pos / powf(10000.0f, (float)(j + 2) * (1.0f / D_MODEL));

    float4 o;
    o.x = ev.x * 32.0f + sinf(ang0);
    o.y = ev.y * 32.0f + cosf(ang0);
    o.z = ev.z * 32.0f + sinf(ang1);
    o.w = ev.w * 32.0f + cosf(ang1);
    *(float4*)(g_h + (size_t)t * D_MODEL + j) = o;
}

// ---------------- weight transposes: dst[n][k] = tf32round(src[k][n]) ----------------
__global__ void tposew_kernel(const float* __restrict__ src, float* __restrict__ dst,
                              int R, int C, size_t sstride, size_t dstride)
{
    __shared__ float t[32][33];
    int z = blockIdx.z;
    src += (size_t)z * sstride;
    dst += (size_t)z * dstride;
    int c0 = blockIdx.x * 32, r0 = blockIdx.y * 32;
    int tx = threadIdx.x, ty = threadIdx.y;   // 32 x 8
    #pragma unroll
    for (int i = 0; i < 32; i += 8)
        t[ty + i][tx] = src[(size_t)(r0 + ty + i) * C + c0 + tx];
    __syncthreads();
    #pragma unroll
    for (int i = 0; i < 32; i += 8)
        dst[(size_t)(c0 + ty + i) * R + r0 + tx] = tf32i(t[tx][ty + i]);
}

// QKV pack: g_wqkv[l][sel*1024 + h*64 + d][k] = tf32round(W[l][h][k][d])
__global__ void tposeqkv_kernel(const float* __restrict__ Wq, const float* __restrict__ Wk,
                                const float* __restrict__ Wv)
{
    __shared__ float t[32][33];
    int z = blockIdx.z;            // l*48 + sel*16 + h
    int l = z / 48, rem = z % 48, sel = rem >> 4, h = rem & 15;
    const float* W = (sel == 0) ? Wq : (sel == 1) ? Wk : Wv;
    const float* src = W + ((size_t)(l * 16 + h)) * D_MODEL * D_QKV;   // [1024 k][64 d]
    float* dst = g_wqkv + (size_t)l * 3 * D_MODEL * D_MODEL
               + (size_t)(sel * 1024 + h * 64) * D_MODEL;              // [d][k]
    int c0 = blockIdx.x * 32, r0 = blockIdx.y * 32;                    // C=64, R=1024
    int tx = threadIdx.x, ty = threadIdx.y;
    #pragma unroll
    for (int i = 0; i < 32; i += 8)
        t[ty + i][tx] = src[(size_t)(r0 + ty + i) * 64 + c0 + tx];
    __syncthreads();
    #pragma unroll
    for (int i = 0; i < 32; i += 8)
        dst[(size_t)(c0 + ty + i) * D_MODEL + r0 + tx] = tf32i(t[tx][ty + i]);
}

// ---------------- tensor-core GEMM via mma.sync tf32 ----------------
// C[M,N] = A[M,K] @ Bt[N,K]^T.  CTA 128x128, 8 warps (4m x 2n), warp 32x64,
// BK=16 (two k8 steps). Synchronous double buffer: LDG->regs prefetch, STS.
// Stride-20 SMEM rows: fragment reads conflict-free (banks {0,20,8,28,...}).
#define FLG_RELU 1

__global__ void __launch_bounds__(256)
tgemm_kernel(const float* __restrict__ A, const float* __restrict__ Bt,
             const float* __restrict__ bias, float* __restrict__ C,
             int M, int N, int K, int flags)
{
    __shared__ float As[2][128][20];   // 10240 B per stage
    __shared__ float Bs[2][128][20];   // total static smem 40960 B < 48K

    const int tid  = threadIdx.x;
    const int wid  = tid >> 5;
    const int lane = tid & 31;
    const int grp  = lane >> 2;         // 0..7
    const int qid  = lane & 3;          // 0..3
    const int wm   = (wid >> 1) * 32;   // 4 m-warps
    const int wn   = (wid & 1) * 64;    // 2 n-warps

    const float* Ab = A  + (size_t)blockIdx.y * 128 * K;
    const float* Bb = Bt + (size_t)blockIdx.x * 128 * K;

    const int lrow = tid >> 1;          // 0..127
    const int lcol = (tid & 1) * 8;     // 0 or 8

    float acc[2][8][4];
    #pragma unroll
    for (int mt = 0; mt < 2; mt++)
        #pragma unroll
        for (int nt = 0; nt < 8; nt++)
            #pragma unroll
            for (int i = 0; i < 4; i++) acc[mt][nt][i] = 0.0f;

    // prologue: chunk 0 -> stage 0 (round A at STS; B already rounded)
    {
        float4 a0 = *(const float4*)(Ab + (size_t)lrow * K + lcol);
        float4 a1 = *(const float4*)(Ab + (size_t)lrow * K + lcol + 4);
        float4 b0 = *(const float4*)(Bb + (size_t)lrow * K + lcol);
        float4 b1 = *(const float4*)(Bb + (size_t)lrow * K + lcol + 4);
        As[0][lrow][lcol + 0] = tf32i(a0.x); As[0][lrow][lcol + 1] = tf32i(a0.y);
        As[0][lrow][lcol + 2] = tf32i(a0.z); As[0][lrow][lcol + 3] = tf32i(a0.w);
        As[0][lrow][lcol + 4] = tf32i(a1.x); As[0][lrow][lcol + 5] = tf32i(a1.y);
        As[0][lrow][lcol + 6] = tf32i(a1.z); As[0][lrow][lcol + 7] = tf32i(a1.w);
        *(float4*)&Bs[0][lrow][lcol]     = b0;
        *(float4*)&Bs[0][lrow][lcol + 4] = b1;
    }
    __syncthreads();

    const int CH = K >> 4;
    for (int c = 0; c < CH; c++) {
        int s = c & 1;
        float4 na0, na1, nb0, nb1;
        const bool more = (c + 1 < CH);
        if (more) {
            int k0 = (c + 1) << 4;
            na0 = *(const float4*)(Ab + (size_t)lrow * K + k0 + lcol);
            na1 = *(const float4*)(Ab + (size_t)lrow * K + k0 + lcol + 4);
            nb0 = *(const float4*)(Bb + (size_t)lrow * K + k0 + lcol);
            nb1 = *(const float4*)(Bb + (size_t)lrow * K + k0 + lcol + 4);
        }

        #pragma unroll
        for (int ks = 0; ks < 16; ks += 8) {
            uint32_t a[2][4], b[8][2];
            #pragma unroll
            for (int mt = 0; mt < 2; mt++) {
                int r = wm + mt * 16 + grp;
                a[mt][0] = __float_as_uint(As[s][r][ks + qid]);
                a[mt][1] = __float_as_uint(As[s][r + 8][ks + qid]);
                a[mt][2] = __float_as_uint(As[s][r][ks + qid + 4]);
                a[mt][3] = __float_as_uint(As[s][r + 8][ks + qid + 4]);
            }
            #pragma unroll
            for (int nt = 0; nt < 8; nt++) {
                int n = wn + nt * 8 + grp;
                b[nt][0] = __float_as_uint(Bs[s][n][ks + qid]);
                b[nt][1] = __float_as_uint(Bs[s][n][ks + qid + 4]);
            }
            #pragma unroll
            for (int mt = 0; mt < 2; mt++)
                #pragma unroll
                for (int nt = 0; nt < 8; nt++)
                    mma_tf32(acc[mt][nt], a[mt], b[nt]);
        }

        if (more) {
            int ns = s ^ 1;
            __syncthreads();     // all reads of stage ns (iter c-1) done
            As[ns][lrow][lcol + 0] = tf32i(na0.x); As[ns][lrow][lcol + 1] = tf32i(na0.y);
            As[ns][lrow][lcol + 2] = tf32i(na0.z); As[ns][lrow][lcol + 3] = tf32i(na0.w);
            As[ns][lrow][lcol + 4] = tf32i(na1.x); As[ns][lrow][lcol + 5] = tf32i(na1.y);
            As[ns][lrow][lcol + 6] = tf32i(na1.z); As[ns][lrow][lcol + 7] = tf32i(na1.w);
            *(float4*)&Bs[ns][lrow][lcol]     = nb0;
            *(float4*)&Bs[ns][lrow][lcol + 4] = nb1;
            __syncthreads();
        }
    }

    // epilogue: c0,c1 -> (row, 2q),(row, 2q+1); c2,c3 -> row+8
    const bool relu = (flags & FLG_RELU) != 0;
    #pragma unroll
    for (int mt = 0; mt < 2; mt++) {
        #pragma unroll
        for (int nt = 0; nt < 8; nt++) {
            int row = blockIdx.y * 128 + wm + mt * 16 + grp;
            int col = blockIdx.x * 128 + wn + nt * 8 + qid * 2;
            float v0 = acc[mt][nt][0], v1 = acc[mt][nt][1];
            float v2 = acc[mt][nt][2], v3 = acc[mt][nt][3];
            if (bias) {
                float b0 = bias[col], b1 = bias[col + 1];
                v0 += b0; v1 += b1; v2 += b0; v3 += b1;
            }
            if (relu) {
                v0 = fmaxf(v0, 0.0f); v1 = fmaxf(v1, 0.0f);
                v2 = fmaxf(v2, 0.0f); v3 = fmaxf(v3, 0.0f);
            }
            *(float2*)(C + (size_t)row * N + col)       = make_float2(v0, v1);
            *(float2*)(C + (size_t)(row + 8) * N + col) = make_float2(v2, v3);
        }
    }
}

// ---------------- fused attention (R1-identical) ----------------
#define AQ 128
#define AK 64
__global__ void __launch_bounds__(128)
attn_kernel(const int* __restrict__ mask)
{
    __shared__ float Ks[AK][D_QKV];
    __shared__ float Vs[AK][D_QKV];
    __shared__ unsigned char Ms[AQ][AK];

    const int tid  = threadIdx.x;
    const int bh   = blockIdx.y;
    const int b    = bh >> 4;
    const int h    = bh & 15;
    const int q0   = blockIdx.x * AQ;
    const int qrow = q0 + tid;

    const float* qp = g_qkv + (size_t)(b * SEQ + qrow) * (3 * D_MODEL) + h * 64;
    float q[64];
    #pragma unroll
    for (int i = 0; i < 16; i++) {
        float4 v = *(const float4*)(qp + i * 4);
        q[i*4+0] = v.x; q[i*4+1] = v.y; q[i*4+2] = v.z; q[i*4+3] = v.w;
    }
    float acc[64];
    #pragma unroll
    for (int i = 0; i < 64; i++) acc[i] = 0.0f;
    float m_run = -1e30f, l_run = 0.0f;

    const int* mb = mask + (size_t)b * SEQ * SEQ;

    for (int j0 = 0; j0 < SEQ; j0 += AK) {
        #pragma unroll
        for (int it = 0; it < 8; it++) {
            int idx = tid + it * 128;
            int r = idx >> 4;
            int c = (idx & 15) << 2;
            const float* kp = g_qkv + (size_t)(b * SEQ + j0 + r) * (3 * D_MODEL) + D_MODEL + h * 64 + c;
            *(float4*)&Ks[r][c] = *(const float4*)kp;
            *(float4*)&Vs[r][c] = *(const float4*)(kp + D_MODEL);
        }
        #pragma unroll
        for (int it = 0; it < 16; it++) {
            int idx = tid + it * 128;
            int r = idx >> 4;
            int c = (idx & 15) << 2;
            int4 mv = *(const int4*)(mb + (size_t)(q0 + r) * SEQ + j0 + c);
            Ms[r][c + 0] = (unsigned char)(mv.x != 0);
            Ms[r][c + 1] = (unsigned char)(mv.y != 0);
            Ms[r][c + 2] = (unsigned char)(mv.z != 0);
            Ms[r][c + 3] = (unsigned char)(mv.w != 0);
        }
        __syncthreads();

        #pragma unroll 1
        for (int j = 0; j < AK; j++) {
            float s = 0.0f;
            #pragma unroll
            for (int d4 = 0; d4 < 16; d4++) {
                float4 kv = *(const float4*)&Ks[j][d4 * 4];
                s += q[d4*4+0]*kv.x + q[d4*4+1]*kv.y + q[d4*4+2]*kv.z + q[d4*4+3]*kv.w;
            }
            s = Ms[tid][j] ? s * 0.125f : -1e9f;
            if (s > m_run) {
                float corr = __expf(m_run - s);
                m_run = s;
                l_run *= corr;
                #pragma unroll
                for (int d = 0; d < 64; d++) acc[d] *= corr;
            }
            float p = __expf(s - m_run);
            l_run += p;
            #pragma unroll
            for (int d4 = 0; d4 < 16; d4++) {
                float4 vv = *(const float4*)&Vs[j][d4 * 4];
                acc[d4*4+0] += p * vv.x;
                acc[d4*4+1] += p * vv.y;
                acc[d4*4+2] += p * vv.z;
                acc[d4*4+3] += p * vv.w;
            }
        }
        __syncthreads();
    }

    float inv = 1.0f / l_run;
    float* op = g_ctx + (size_t)(b * SEQ + qrow) * D_MODEL + h * 64;
    #pragma unroll
    for (int i = 0; i < 16; i++) {
        float4 v;
        v.x = acc[i*4+0] * inv; v.y = acc[i*4+1] * inv;
        v.z = acc[i*4+2] * inv; v.w = acc[i*4+3] * inv;
        *(float4*)(op + i * 4) = v;
    }
}

// ---------------- residual add + layernorm (R1-identical) ----------------
__global__ void ln_kernel(const float* __restrict__ resid, const float* __restrict__ add,
                          const float* __restrict__ sc, const float* __restrict__ bi,
                          float* __restrict__ out)
{
    __shared__ float ssum[8], ssq[8];
    int row = blockIdx.x, tid = threadIdx.x;
    int c = tid * 4;
    float4 hv = *(const float4*)(resid + (size_t)row * D_MODEL + c);
    float4 av = *(const float4*)(add   + (size_t)row * D_MODEL + c);
    float4 r = make_float4(hv.x + av.x, hv.y + av.y, hv.z + av.z, hv.w + av.w);
    float s = r.x + r.y + r.z + r.w;
    float qq = r.x*r.x + r.y*r.y + r.z*r.z + r.w*r.w;
    #pragma unroll
    for (int o = 16; o > 0; o >>= 1) {
        s  += __shfl_xor_sync(0xffffffffu, s,  o);
        qq += __shfl_xor_sync(0xffffffffu, qq, o);
    }
    int w = tid >> 5;
    if ((tid & 31) == 0) { ssum[w] = s; ssq[w] = qq; }
    __syncthreads();
    float ts = 0.0f, tq = 0.0f;
    #pragma unroll
    for (int i = 0; i < 8; i++) { ts += ssum[i]; tq += ssq[i]; }
    float mu   = ts * (1.0f / D_MODEL);
    float var  = tq * (1.0f / D_MODEL) - mu * mu;
    float rstd = rsqrtf(var + 1e-5f);
    float4 scv = *(const float4*)(sc + c);
    float4 biv = *(const float4*)(bi + c);
    float4 o;
    o.x = (r.x - mu) * rstd * scv.x + biv.x;
    o.y = (r.y - mu) * rstd * scv.y + biv.y;
    o.z = (r.z - mu) * rstd * scv.z + biv.z;
    o.w = (r.w - mu) * rstd * scv.w + biv.w;
    *(float4*)(out + (size_t)row * D_MODEL + c) = o;
}

// ---------------- final head (R1-identical) ----------------
__global__ void head_kernel(const float* __restrict__ ow, const float* __restrict__ ob,
                            float* __restrict__ out)
{
    int tid = threadIdx.x;           // 128 = 8 batches * 16 actions
    int b = tid >> 4, a = tid & 15;
    const float* hr = g_h + ((size_t)b * SEQ + (SEQ - 1)) * D_MODEL;
    float acc = 0.0f;
    for (int k = 0; k < D_MODEL; k++) acc += hr[k] * ow[k * N_ACTIONS + a];
    acc += ob[a];
    float m = acc;
    #pragma unroll
    for (int o = 8; o > 0; o >>= 1) m = fmaxf(m, __shfl_xor_sync(0xffffffffu, m, o, 16));
    float e = expf(acc - m), sum = e;
    #pragma unroll
    for (int o = 8; o > 0; o >>= 1) sum += __shfl_xor_sync(0xffffffffu, sum, o, 16);
    out[b * N_ACTIONS + a] = acc - m - logf(sum);
}

// ---------------- launch ----------------
extern "C" void kernel_launch(void* const* d_in, const int* in_sizes, int n_in,
                              void* d_out, int out_size)
{
    const int*   x     = (const int*)d_in[0];
    const int*   mask  = (const int*)d_in[1];
    const float* embed = (const float*)d_in[2];
    const float* Wq    = (const float*)d_in[3];
    const float* Wk    = (const float*)d_in[4];
    const float* Wv    = (const float*)d_in[5];
    const float* Wo_w  = (const float*)d_in[6];
    const float* Wo_b  = (const float*)d_in[7];
    const float* ln1s  = (const float*)d_in[8];
    const float* ln1b  = (const float*)d_in[9];
    const float* ffw1  = (const float*)d_in[10];
    const float* ffb1  = (const float*)d_in[11];
    const float* ffw2  = (const float*)d_in[12];
    const float* ffb2  = (const float*)d_in[13];
    const float* ln2s  = (const float*)d_in[14];
    const float* ln2b  = (const float*)d_in[15];
    const float* ow    = (const float*)d_in[16];
    const float* ob    = (const float*)d_in[17];
    float* out = (float*)d_out;

    float *h, *qkv, *ctx, *buf1, *buf2, *wqkv, *wot, *w1t, *w2t;
    cudaGetSymbolAddress((void**)&h,    g_h);
    cudaGetSymbolAddress((void**)&qkv,  g_qkv);
    cudaGetSymbolAddress((void**)&ctx,  g_ctx);
    cudaGetSymbolAddress((void**)&buf1, g_buf1);
    cudaGetSymbolAddress((void**)&buf2, g_buf2);
    cudaGetSymbolAddress((void**)&wqkv, g_wqkv);
    cudaGetSymbolAddress((void**)&wot,  g_wot);
    cudaGetSymbolAddress((void**)&w1t,  g_w1t);
    cudaGetSymbolAddress((void**)&w2t,  g_w2t);

    // per-launch weight packs (transposed + tf32-rounded)
    dim3 tb(32, 8);
    tposeqkv_kernel<<<dim3(2, 32, N_LAYERS * 48), tb>>>(Wq, Wk, Wv);
    tposew_kernel<<<dim3(32, 32, N_LAYERS), tb>>>(Wo_w, wot, 1024, 1024,
        (size_t)D_MODEL * D_MODEL, (size_t)D_MODEL * D_MODEL);
    tposew_kernel<<<dim3(128, 32, N_LAYERS), tb>>>(ffw1, w1t, 1024, 4096,
        (size_t)D_MODEL * D_FF, (size_t)D_FF * D_MODEL);
    tposew_kernel<<<dim3(32, 128, N_LAYERS), tb>>>(ffw2, w2t, 4096, 1024,
        (size_t)D_FF * D_MODEL, (size_t)D_MODEL * D_FF);

    embed_kernel<<<TOK, 256>>>(x, embed);

    for (int i = 0; i < N_LAYERS; i++) {
        tgemm_kernel<<<dim3((3 * D_MODEL) / 128, TOK / 128), 256>>>(
            h, wqkv + (size_t)i * 3 * D_MODEL * D_MODEL, nullptr, qkv,
            TOK, 3 * D_MODEL, D_MODEL, 0);
        attn_kernel<<<dim3(SEQ / AQ, BATCH * N_HEADS), 128>>>(mask);
        tgemm_kernel<<<dim3(D_MODEL / 128, TOK / 128), 256>>>(
            ctx, wot + (size_t)i * D_MODEL * D_MODEL, Wo_b + (size_t)i * D_MODEL, buf1,
            TOK, D_MODEL, D_MODEL, 0);
        ln_kernel<<<TOK, 256>>>(h, buf1, ln1s + (size_t)i * D_MODEL, ln1b + (size_t)i * D_MODEL, h);
        tgemm_kernel<<<dim3(D_FF / 128, TOK / 128), 256>>>(
            h, w1t + (size_t)i * D_FF * D_MODEL, ffb1 + (size_t)i * D_FF, buf1,
            TOK, D_FF, D_MODEL, FLG_RELU);
        tgemm_kernel<<<dim3(D_MODEL / 128, TOK / 128), 256>>>(
            buf1, w2t + (size_t)i * D_MODEL * D_FF, ffb2 + (size_t)i * D_MODEL, buf2,
            TOK, D_MODEL, D_FF, 0);
        ln_kernel<<<TOK, 256>>>(h, buf2, ln2s + (size_t)i * D_MODEL, ln2b + (size_t)i * D_MODEL, h);
    }

    head_kernel<<<1, 128>>>(ow, ob, out);
}